// round 11
// baseline (speedup 1.0000x reference)
#include <cuda_runtime.h>
#include <math.h>
#include <stdint.h>

#define CIN 48
#define CB  8
#define H   4096
#define HV  (H/4)          // 1024 16B-elements per channel row
#define CH_BYTES (H * 4)   // 16 KB per channel row
#define NTHREADS 1024
#define NWARPS   (NTHREADS/32)
#define NPAIR    36        // upper-triangle incl. diag of 8x8
#define SCALE    0.35355339059327373f   // 1/sqrt(8)
#define PD       8         // L2 prefetch distance (channels)

typedef unsigned long long ull;

// packed fp32x2 FMA / MUL (SASS FFMA2 — PTX-only on sm_103a)
__device__ __forceinline__ ull fma2(ull a, ull b, ull c) {
    ull d;
    asm("fma.rn.f32x2 %0, %1, %2, %3;" : "=l"(d) : "l"(a), "l"(b), "l"(c));
    return d;
}
__device__ __forceinline__ ull mul2(ull a, ull b) {
    ull d;
    asm("mul.rn.f32x2 %0, %1, %2;" : "=l"(d) : "l"(a), "l"(b));
    return d;
}
__device__ __forceinline__ void unpack2(ull v, float& lo, float& hi) {
    asm("mov.b64 {%0, %1}, %2;" : "=f"(lo), "=f"(hi) : "l"(v));
}
__device__ __forceinline__ ull dup_f32(float f) {
    uint32_t u = __float_as_uint(f);
    return ((ull)u << 32) | (ull)u;
}
// bulk L2 prefetch: one instruction pulls a whole region DRAM->L2
__device__ __forceinline__ void bulk_prefetch_l2(const void* p, uint32_t bytes) {
    asm volatile("cp.async.bulk.prefetch.L2.global [%0], %1;"
                 :: "l"(p), "r"(bytes) : "memory");
}

__global__ __launch_bounds__(NTHREADS, 1)
void ultimus_kernel(const float* __restrict__ x,
                    const float* __restrict__ wd,   // [8,48]
                    const float* __restrict__ wu,   // [48,8]
                    float* __restrict__ out)
{
    __shared__ ull   s_wdd[CIN * CB];          // transposed dup pairs [c][o]
    __shared__ float s_gpart[NWARPS * NPAIR];
    __shared__ float s_G[CB * CB];
    __shared__ float s_AM[CB * CB];
    __shared__ ull   s_W2d[CIN * CB];          // dup pairs [c][o]

    const int b    = blockIdx.x;
    const int t    = threadIdx.x;
    const int lane = t & 31;
    const int warp = t >> 5;

    // transposed duplicated down-weights: s_wdd[c*CB+o] = {wd[o][c], wd[o][c]}
    if (t < CB * CIN) {
        int o = t / CIN, c = t % CIN;
        s_wdd[c * CB + o] = dup_f32(wd[t]);
    }

    const float* xb = x + (size_t)b * CIN * H;
    const double2* __restrict__ x2 = (const double2*)xb;

    // prime the L2 prefetch pipeline: channels 0..PD-1 (one bulk op each)
    if (t == 0) {
        #pragma unroll
        for (int j = 0; j < PD; j++)
            bulk_prefetch_l2(xb + j * H, CH_BYTES);
    }
    __syncthreads();

    // ---------------- Pass 1: kqv = w_down @ x (f32x2 accumulators) --------
    ull acc2[CB][2];
    #pragma unroll
    for (int o = 0; o < CB; o++) { acc2[o][0] = 0ull; acc2[o][1] = 0ull; }

    #pragma unroll
    for (int c = 0; c < CIN; c++) {            // FULL unroll: imm addresses
        if (c + PD < CIN && t == 0)
            bulk_prefetch_l2(xb + (c + PD) * H, CH_BYTES);
        double2 xv = __ldcs(&x2[c * HV + t]);
        ull xlo = __double_as_longlong(xv.x);
        ull xhi = __double_as_longlong(xv.y);
        const ulonglong2* wp = (const ulonglong2*)(s_wdd + c * CB);
        #pragma unroll
        for (int oo = 0; oo < CB / 2; oo++) {
            ulonglong2 w2v = wp[oo];           // LDS.128: weights o=2oo,2oo+1
            acc2[2*oo  ][0] = fma2(w2v.x, xlo, acc2[2*oo  ][0]);
            acc2[2*oo  ][1] = fma2(w2v.x, xhi, acc2[2*oo  ][1]);
            acc2[2*oo+1][0] = fma2(w2v.y, xlo, acc2[2*oo+1][0]);
            acc2[2*oo+1][1] = fma2(w2v.y, xhi, acc2[2*oo+1][1]);
        }
    }

    // ---------------- Gram: G[i][j] = sum_h kqv_i * kqv_j ------------------
    {
        int base = 0;
        #pragma unroll
        for (int i = 0; i < CB; i++) {
            #pragma unroll
            for (int j = i; j < CB; j++) {
                ull p = mul2(acc2[i][0], acc2[j][0]);
                p = fma2(acc2[i][1], acc2[j][1], p);
                float plo, phi;
                unpack2(p, plo, phi);
                float s = plo + phi;
                #pragma unroll
                for (int off = 16; off > 0; off >>= 1)
                    s += __shfl_xor_sync(0xffffffffu, s, off);
                if (lane == 0) s_gpart[warp * NPAIR + base] = s;
                base++;
            }
        }
    }
    __syncthreads();

    // reduce 32 warp partials -> full symmetric G
    if (t < NPAIR) {
        float s = 0.f;
        #pragma unroll
        for (int w = 0; w < NWARPS; w++) s += s_gpart[w * NPAIR + t];
        int i = 0, rem = t;
        while (rem >= CB - i) { rem -= CB - i; i++; }
        int j = i + rem;
        s_G[i * CB + j] = s;
        s_G[j * CB + i] = s;
    }
    __syncthreads();

    // ---------------- Softmax rows of G*SCALE -> AM -------------------------
    if (t < CB) {
        float v[CB];
        float m = -1e30f;
        #pragma unroll
        for (int j = 0; j < CB; j++) {
            v[j] = s_G[t * CB + j] * SCALE;
            m = fmaxf(m, v[j]);
        }
        float sum = 0.f;
        #pragma unroll
        for (int j = 0; j < CB; j++) {
            v[j] = __expf(v[j] - m);
            sum += v[j];
        }
        float inv = 1.f / sum;
        #pragma unroll
        for (int j = 0; j < CB; j++) s_AM[t * CB + j] = v[j] * inv;
    }
    __syncthreads();

    // ---------------- W2[c][j] = sum_o wu[c][o] * AM[o][j], duplicated ------
    if (t < CIN * CB) {
        int c = t >> 3, j = t & 7;
        float s = 0.f;
        #pragma unroll
        for (int o = 0; o < CB; o++) s += wu[c * CB + o] * s_AM[o * CB + j];
        s_W2d[c * CB + j] = dup_f32(s);
    }
    __syncthreads();

    // ---------------- Pass 2: out[c][h] = sum_j W2[c][j] * kqv[j][h] --------
    double2* __restrict__ out2 = (double2*)(out + (size_t)b * CIN * H);

    #pragma unroll
    for (int c = 0; c < CIN; c++) {            // FULL unroll: imm addresses
        const ulonglong2* wp = (const ulonglong2*)(s_W2d + c * CB);
        ulonglong2 wv = wp[0];
        ull r0 = mul2(wv.x, acc2[0][0]);
        ull r1 = mul2(wv.x, acc2[0][1]);
        r0 = fma2(wv.y, acc2[1][0], r0);
        r1 = fma2(wv.y, acc2[1][1], r1);
        #pragma unroll
        for (int oo = 1; oo < CB / 2; oo++) {
            wv = wp[oo];
            r0 = fma2(wv.x, acc2[2*oo  ][0], r0);
            r1 = fma2(wv.x, acc2[2*oo  ][1], r1);
            r0 = fma2(wv.y, acc2[2*oo+1][0], r0);
            r1 = fma2(wv.y, acc2[2*oo+1][1], r1);
        }
        double2 rv;
        rv.x = __longlong_as_double((long long)r0);
        rv.y = __longlong_as_double((long long)r1);
        __stwt(&out2[c * HV + t], rv);
    }
}

extern "C" void kernel_launch(void* const* d_in, const int* in_sizes, int n_in,
                              void* d_out, int out_size)
{
    const float* x  = (const float*)d_in[0];   // [256, 48, 4096, 1]
    const float* wd = (const float*)d_in[1];   // [8, 48]
    const float* wu = (const float*)d_in[2];   // [48, 8]
    float* out = (float*)d_out;                // [256, 48, 4096, 1]

    ultimus_kernel<<<256, NTHREADS>>>(x, wd, wu, out);
}

// round 12
// speedup vs baseline: 1.1596x; 1.1596x over previous
#include <cuda_runtime.h>
#include <math.h>
#include <stdint.h>

#define CIN 48
#define CB  8
#define H   4096
#define HV  (H/4)          // 1024 16B-elements per channel row
#define NTHREADS 1024
#define NWARPS   (NTHREADS/32)
#define NPAIR    36        // upper-triangle incl. diag of 8x8
#define SCALE    0.35355339059327373f   // 1/sqrt(8)
#define PD       8         // L2 prefetch distance (channels)

typedef unsigned long long ull;

// packed fp32x2 FMA / MUL (SASS FFMA2 — PTX-only on sm_103a)
__device__ __forceinline__ ull fma2(ull a, ull b, ull c) {
    ull d;
    asm("fma.rn.f32x2 %0, %1, %2, %3;" : "=l"(d) : "l"(a), "l"(b), "l"(c));
    return d;
}
__device__ __forceinline__ ull mul2(ull a, ull b) {
    ull d;
    asm("mul.rn.f32x2 %0, %1, %2;" : "=l"(d) : "l"(a), "l"(b));
    return d;
}
__device__ __forceinline__ void unpack2(ull v, float& lo, float& hi) {
    asm("mov.b64 {%0, %1}, %2;" : "=f"(lo), "=f"(hi) : "l"(v));
}
__device__ __forceinline__ ull dup_f32(float f) {
    uint32_t u = __float_as_uint(f);
    return ((ull)u << 32) | (ull)u;
}
__device__ __forceinline__ void prefetch_l2(const void* p) {
    asm volatile("prefetch.global.L2 [%0];" :: "l"(p));
}

__global__ __launch_bounds__(NTHREADS, 1)
void ultimus_kernel(const float* __restrict__ x,
                    const float* __restrict__ wd,   // [8,48]
                    const float* __restrict__ wu,   // [48,8]
                    float* __restrict__ out)
{
    __shared__ ull   s_wdd[CIN * CB];          // transposed dup pairs [c][o]
    __shared__ float s_gpart[NWARPS * NPAIR];
    __shared__ float s_G[CB * CB];
    __shared__ float s_AM[CB * CB];
    __shared__ ull   s_W2d[CIN * CB];          // dup pairs [c][o]

    const int b    = blockIdx.x;
    const int t    = threadIdx.x;
    const int lane = t & 31;
    const int warp = t >> 5;

    // transposed duplicated down-weights: s_wdd[c*CB+o] = {wd[o][c], wd[o][c]}
    if (t < CB * CIN) {
        int o = t / CIN, c = t % CIN;
        s_wdd[c * CB + o] = dup_f32(wd[t]);
    }

    const double2* __restrict__ x2 = (const double2*)(x + (size_t)b * CIN * H);
    const bool pf = ((t & 7) == 0);            // one prefetch per 128B line

    // prime the L2 prefetch pipeline: channels 0..PD-1 (immediate offsets)
    if (pf) {
        #pragma unroll
        for (int j = 0; j < PD; j++)
            prefetch_l2(&x2[j * HV + t]);
    }
    __syncthreads();

    // ---------------- Pass 1: kqv = w_down @ x (f32x2 accumulators) --------
    ull acc2[CB][2];
    #pragma unroll
    for (int o = 0; o < CB; o++) { acc2[o][0] = 0ull; acc2[o][1] = 0ull; }

    // manual 2-deep load pipeline: always one demand load in flight ahead
    double2 xv_next = __ldcs(&x2[t]);

    #pragma unroll
    for (int c = 0; c < CIN; c++) {            // FULL unroll: imm addresses
        double2 xv = xv_next;
        if (c + 1 < CIN)
            xv_next = __ldcs(&x2[(c + 1) * HV + t]);
        if (c + PD < CIN && pf)
            prefetch_l2(&x2[(c + PD) * HV + t]);
        ull xlo = __double_as_longlong(xv.x);
        ull xhi = __double_as_longlong(xv.y);
        const ulonglong2* wp = (const ulonglong2*)(s_wdd + c * CB);
        #pragma unroll
        for (int oo = 0; oo < CB / 2; oo++) {
            ulonglong2 w2v = wp[oo];           // LDS.128: weights o=2oo,2oo+1
            acc2[2*oo  ][0] = fma2(w2v.x, xlo, acc2[2*oo  ][0]);
            acc2[2*oo  ][1] = fma2(w2v.x, xhi, acc2[2*oo  ][1]);
            acc2[2*oo+1][0] = fma2(w2v.y, xlo, acc2[2*oo+1][0]);
            acc2[2*oo+1][1] = fma2(w2v.y, xhi, acc2[2*oo+1][1]);
        }
    }

    // ---------------- Gram: G[i][j] = sum_h kqv_i * kqv_j ------------------
    {
        int base = 0;
        #pragma unroll
        for (int i = 0; i < CB; i++) {
            #pragma unroll
            for (int j = i; j < CB; j++) {
                ull p = mul2(acc2[i][0], acc2[j][0]);
                p = fma2(acc2[i][1], acc2[j][1], p);
                float plo, phi;
                unpack2(p, plo, phi);
                float s = plo + phi;
                #pragma unroll
                for (int off = 16; off > 0; off >>= 1)
                    s += __shfl_xor_sync(0xffffffffu, s, off);
                if (lane == 0) s_gpart[warp * NPAIR + base] = s;
                base++;
            }
        }
    }
    __syncthreads();

    // reduce 32 warp partials -> full symmetric G
    if (t < NPAIR) {
        float s = 0.f;
        #pragma unroll
        for (int w = 0; w < NWARPS; w++) s += s_gpart[w * NPAIR + t];
        int i = 0, rem = t;
        while (rem >= CB - i) { rem -= CB - i; i++; }
        int j = i + rem;
        s_G[i * CB + j] = s;
        s_G[j * CB + i] = s;
    }
    __syncthreads();

    // ---------------- Softmax rows of G*SCALE -> AM -------------------------
    if (t < CB) {
        float v[CB];
        float m = -1e30f;
        #pragma unroll
        for (int j = 0; j < CB; j++) {
            v[j] = s_G[t * CB + j] * SCALE;
            m = fmaxf(m, v[j]);
        }
        float sum = 0.f;
        #pragma unroll
        for (int j = 0; j < CB; j++) {
            v[j] = __expf(v[j] - m);
            sum += v[j];
        }
        float inv = 1.f / sum;
        #pragma unroll
        for (int j = 0; j < CB; j++) s_AM[t * CB + j] = v[j] * inv;
    }
    __syncthreads();

    // ---------------- W2[c][j] = sum_o wu[c][o] * AM[o][j], duplicated ------
    if (t < CIN * CB) {
        int c = t >> 3, j = t & 7;
        float s = 0.f;
        #pragma unroll
        for (int o = 0; o < CB; o++) s += wu[c * CB + o] * s_AM[o * CB + j];
        s_W2d[c * CB + j] = dup_f32(s);
    }
    __syncthreads();

    // ---------------- Pass 2: out[c][h] = sum_j W2[c][j] * kqv[j][h] --------
    double2* __restrict__ out2 = (double2*)(out + (size_t)b * CIN * H);

    #pragma unroll
    for (int c = 0; c < CIN; c++) {            // FULL unroll: imm addresses
        const ulonglong2* wp = (const ulonglong2*)(s_W2d + c * CB);
        ulonglong2 wv = wp[0];
        ull r0 = mul2(wv.x, acc2[0][0]);
        ull r1 = mul2(wv.x, acc2[0][1]);
        r0 = fma2(wv.y, acc2[1][0], r0);
        r1 = fma2(wv.y, acc2[1][1], r1);
        #pragma unroll
        for (int oo = 1; oo < CB / 2; oo++) {
            wv = wp[oo];
            r0 = fma2(wv.x, acc2[2*oo  ][0], r0);
            r1 = fma2(wv.x, acc2[2*oo  ][1], r1);
            r0 = fma2(wv.y, acc2[2*oo+1][0], r0);
            r1 = fma2(wv.y, acc2[2*oo+1][1], r1);
        }
        double2 rv;
        rv.x = __longlong_as_double((long long)r0);
        rv.y = __longlong_as_double((long long)r1);
        __stwt(&out2[c * HV + t], rv);
    }
}

extern "C" void kernel_launch(void* const* d_in, const int* in_sizes, int n_in,
                              void* d_out, int out_size)
{
    const float* x  = (const float*)d_in[0];   // [256, 48, 4096, 1]
    const float* wd = (const float*)d_in[1];   // [8, 48]
    const float* wu = (const float*)d_in[2];   // [48, 8]
    float* out = (float*)d_out;                // [256, 48, 4096, 1]

    ultimus_kernel<<<256, NTHREADS>>>(x, wd, wu, out);
}

// round 13
// speedup vs baseline: 1.1854x; 1.0222x over previous
#include <cuda_runtime.h>
#include <math.h>
#include <stdint.h>

#define CIN 48
#define CB  8
#define H   4096
#define HV  (H/4)          // 1024 16B-elements per channel row
#define NTHREADS 1024
#define NWARPS   (NTHREADS/32)
#define NPAIR    36        // upper-triangle incl. diag of 8x8
#define SCALE    0.35355339059327373f   // 1/sqrt(8)
#define PD       8         // L2 prefetch distance (channels)

typedef unsigned long long ull;

// packed fp32x2 FMA / MUL (SASS FFMA2 — PTX-only on sm_103a)
__device__ __forceinline__ ull fma2(ull a, ull b, ull c) {
    ull d;
    asm("fma.rn.f32x2 %0, %1, %2, %3;" : "=l"(d) : "l"(a), "l"(b), "l"(c));
    return d;
}
__device__ __forceinline__ ull mul2(ull a, ull b) {
    ull d;
    asm("mul.rn.f32x2 %0, %1, %2;" : "=l"(d) : "l"(a), "l"(b));
    return d;
}
__device__ __forceinline__ void unpack2(ull v, float& lo, float& hi) {
    asm("mov.b64 {%0, %1}, %2;" : "=f"(lo), "=f"(hi) : "l"(v));
}
__device__ __forceinline__ ull dup_f32(float f) {
    uint32_t u = __float_as_uint(f);
    return ((ull)u << 32) | (ull)u;
}
__device__ __forceinline__ void prefetch_l2(const void* p) {
    asm volatile("prefetch.global.L2 [%0];" :: "l"(p));
}

__global__ __launch_bounds__(NTHREADS, 1)
void ultimus_kernel(const float* __restrict__ x,
                    const float* __restrict__ wd,   // [8,48]
                    const float* __restrict__ wu,   // [48,8]
                    float* __restrict__ out)
{
    __shared__ ull   s_wdd[CIN * CB];          // transposed dup pairs [c][o]
    __shared__ float s_gpart[NWARPS * NPAIR];
    __shared__ float s_G[CB * CB];
    __shared__ float s_AM[CB * CB];
    __shared__ ull   s_W2d[CIN * CB];          // dup pairs [c][o]

    const int b    = blockIdx.x;
    const int t    = threadIdx.x;
    const int lane = t & 31;
    const int warp = t >> 5;

    // transposed duplicated down-weights: s_wdd[c*CB+o] = {wd[o][c], wd[o][c]}
    if (t < CB * CIN) {
        int o = t / CIN, c = t % CIN;
        s_wdd[c * CB + o] = dup_f32(wd[t]);
    }

    const double2* __restrict__ x2 = (const double2*)(x + (size_t)b * CIN * H);
    const bool pf = ((t & 7) == 0);            // one prefetch per 128B line

    // prime the L2 prefetch pipeline: channels 0..PD-1 (immediate offsets)
    if (pf) {
        #pragma unroll
        for (int j = 0; j < PD; j++)
            prefetch_l2(&x2[j * HV + t]);
    }
    __syncthreads();

    // ---------------- Pass 1: kqv = w_down @ x (f32x2 accumulators) --------
    ull acc2[CB][2];
    #pragma unroll
    for (int o = 0; o < CB; o++) { acc2[o][0] = 0ull; acc2[o][1] = 0ull; }

    // manual 3-deep load pipeline: two demand loads in flight ahead
    double2 xv_n1 = __ldcs(&x2[t]);
    double2 xv_n2 = __ldcs(&x2[HV + t]);

    #pragma unroll
    for (int c = 0; c < CIN; c++) {            // FULL unroll: imm addresses
        double2 xv = xv_n1;
        xv_n1 = xv_n2;
        if (c + 2 < CIN)
            xv_n2 = __ldcs(&x2[(c + 2) * HV + t]);
        if (c + PD < CIN && pf)
            prefetch_l2(&x2[(c + PD) * HV + t]);
        ull xlo = __double_as_longlong(xv.x);
        ull xhi = __double_as_longlong(xv.y);
        const ulonglong2* wp = (const ulonglong2*)(s_wdd + c * CB);
        #pragma unroll
        for (int oo = 0; oo < CB / 2; oo++) {
            ulonglong2 w2v = wp[oo];           // LDS.128: weights o=2oo,2oo+1
            acc2[2*oo  ][0] = fma2(w2v.x, xlo, acc2[2*oo  ][0]);
            acc2[2*oo  ][1] = fma2(w2v.x, xhi, acc2[2*oo  ][1]);
            acc2[2*oo+1][0] = fma2(w2v.y, xlo, acc2[2*oo+1][0]);
            acc2[2*oo+1][1] = fma2(w2v.y, xhi, acc2[2*oo+1][1]);
        }
    }

    // ---------------- Gram: G[i][j] = sum_h kqv_i * kqv_j ------------------
    {
        int base = 0;
        #pragma unroll
        for (int i = 0; i < CB; i++) {
            #pragma unroll
            for (int j = i; j < CB; j++) {
                ull p = mul2(acc2[i][0], acc2[j][0]);
                p = fma2(acc2[i][1], acc2[j][1], p);
                float plo, phi;
                unpack2(p, plo, phi);
                float s = plo + phi;
                #pragma unroll
                for (int off = 16; off > 0; off >>= 1)
                    s += __shfl_xor_sync(0xffffffffu, s, off);
                if (lane == 0) s_gpart[warp * NPAIR + base] = s;
                base++;
            }
        }
    }
    __syncthreads();

    // reduce 32 warp partials -> full symmetric G
    if (t < NPAIR) {
        float s = 0.f;
        #pragma unroll
        for (int w = 0; w < NWARPS; w++) s += s_gpart[w * NPAIR + t];
        int i = 0, rem = t;
        while (rem >= CB - i) { rem -= CB - i; i++; }
        int j = i + rem;
        s_G[i * CB + j] = s;
        s_G[j * CB + i] = s;
    }
    __syncthreads();

    // ---------------- Softmax rows of G*SCALE -> AM -------------------------
    if (t < CB) {
        float v[CB];
        float m = -1e30f;
        #pragma unroll
        for (int j = 0; j < CB; j++) {
            v[j] = s_G[t * CB + j] * SCALE;
            m = fmaxf(m, v[j]);
        }
        float sum = 0.f;
        #pragma unroll
        for (int j = 0; j < CB; j++) {
            v[j] = __expf(v[j] - m);
            sum += v[j];
        }
        float inv = 1.f / sum;
        #pragma unroll
        for (int j = 0; j < CB; j++) s_AM[t * CB + j] = v[j] * inv;
    }
    __syncthreads();

    // ---------------- W2[c][j] = sum_o wu[c][o] * AM[o][j], duplicated ------
    if (t < CIN * CB) {
        int c = t >> 3, j = t & 7;
        float s = 0.f;
        #pragma unroll
        for (int o = 0; o < CB; o++) s += wu[c * CB + o] * s_AM[o * CB + j];
        s_W2d[c * CB + j] = dup_f32(s);
    }
    __syncthreads();

    // ---------------- Pass 2: out[c][h] = sum_j W2[c][j] * kqv[j][h] --------
    double2* __restrict__ out2 = (double2*)(out + (size_t)b * CIN * H);

    #pragma unroll
    for (int c = 0; c < CIN; c++) {            // FULL unroll: imm addresses
        const ulonglong2* wp = (const ulonglong2*)(s_W2d + c * CB);
        ulonglong2 wv = wp[0];
        ull r0 = mul2(wv.x, acc2[0][0]);
        ull r1 = mul2(wv.x, acc2[0][1]);
        r0 = fma2(wv.y, acc2[1][0], r0);
        r1 = fma2(wv.y, acc2[1][1], r1);
        #pragma unroll
        for (int oo = 1; oo < CB / 2; oo++) {
            wv = wp[oo];
            r0 = fma2(wv.x, acc2[2*oo  ][0], r0);
            r1 = fma2(wv.x, acc2[2*oo  ][1], r1);
            r0 = fma2(wv.y, acc2[2*oo+1][0], r0);
            r1 = fma2(wv.y, acc2[2*oo+1][1], r1);
        }
        double2 rv;
        rv.x = __longlong_as_double((long long)r0);
        rv.y = __longlong_as_double((long long)r1);
        __stwt(&out2[c * HV + t], rv);
    }
}

extern "C" void kernel_launch(void* const* d_in, const int* in_sizes, int n_in,
                              void* d_out, int out_size)
{
    const float* x  = (const float*)d_in[0];   // [256, 48, 4096, 1]
    const float* wd = (const float*)d_in[1];   // [8, 48]
    const float* wu = (const float*)d_in[2];   // [48, 8]
    float* out = (float*)d_out;                // [256, 48, 4096, 1]

    ultimus_kernel<<<256, NTHREADS>>>(x, wd, wu, out);
}